// round 13
// baseline (speedup 1.0000x reference)
#include <cuda_runtime.h>
#include <cuda_fp16.h>
#include <cstdint>

#define DIN     8192
#define DOUT    8192
#define MR      32
#define KSPLIT  8
#define KRANGE  (DIN / KSPLIT)   // 1024
#define KC      64               // k rows per chunk
#define NCHUNKS (KRANGE / KC)    // 16
#define NTILE   128              // n cols per CTA
#define GTHREADS 256

// padded smem row strides (u16 units) -> conflict-free ldmatrix
#define XSTR 72    // 64 k + 8 pad  (144 B)
#define WSTR 136   // 128 n + 8 pad (272 B)

// ---------------- static device scratch (no runtime alloc) ----------------
__device__ float g_partial[KSPLIT * MR * DOUT];  // split-k partials (8MB)

// ---------------- helpers ----------------
__device__ __forceinline__ uint32_t smem_u32(const void* p) {
    uint32_t a;
    asm("{ .reg .u64 t; cvta.to.shared.u64 t, %1; cvt.u32.u64 %0, t; }" : "=r"(a) : "l"(p));
    return a;
}
// packed fp16x2: lo half = f16(a), hi half = f16(b)
__device__ __forceinline__ uint32_t f16pack(float a, float b) {
    __half2 h = __floats2half2_rn(a, b);
    return *reinterpret_cast<uint32_t*>(&h);
}
__device__ __forceinline__ void ldsm4(uint32_t* r, uint32_t addr) {
    asm volatile("ldmatrix.sync.aligned.m8n8.x4.shared.b16 {%0,%1,%2,%3}, [%4];"
        : "=r"(r[0]), "=r"(r[1]), "=r"(r[2]), "=r"(r[3]) : "r"(addr));
}
__device__ __forceinline__ void ldsm4t(uint32_t* r, uint32_t addr) {
    asm volatile("ldmatrix.sync.aligned.m8n8.x4.trans.shared.b16 {%0,%1,%2,%3}, [%4];"
        : "=r"(r[0]), "=r"(r[1]), "=r"(r[2]), "=r"(r[3]) : "r"(addr));
}
__device__ __forceinline__ void mma_f16(float* d, const uint32_t* a, const uint32_t* b) {
    asm volatile("mma.sync.aligned.m16n8k16.row.col.f32.f16.f16.f32 "
        "{%0,%1,%2,%3}, {%4,%5,%6,%7}, {%8,%9}, {%0,%1,%2,%3};"
        : "+f"(d[0]), "+f"(d[1]), "+f"(d[2]), "+f"(d[3])
        : "r"(a[0]), "r"(a[1]), "r"(a[2]), "r"(a[3]), "r"(b[0]), "r"(b[1]));
}

// ---------------------------------------------------------------------------
// Main: fused x fp32->fp16 convert + Q4_0 dequant -> fp16 smem tiles ->
// mma.sync. Single-term: y = x_f16 * w_f16.
// grid = (DOUT/NTILE, KSPLIT), 8 warps. W prefetch interleaved in HALVES so
// the reload of wv[0..3] has a full half-dequant + mma + barriers of latency
// cover; peak register liveness unchanged (8 x float4).
// ---------------------------------------------------------------------------
__global__ void __launch_bounds__(GTHREADS, 2)
gemm_kernel(const float* __restrict__ W, const float* __restrict__ X) {
    __shared__ __align__(16) uint16_t sXH[MR * XSTR];   // 4.5 KB
    __shared__ __align__(16) uint16_t sWH[KC * WSTR];   // 17 KB

    const int tid  = threadIdx.x;
    const int wid  = tid >> 5;
    const int lane = tid & 31;
    const int n0   = blockIdx.x * NTILE;
    const int ks   = blockIdx.y;
    const int k0   = ks * KRANGE;

    const uint32_t xh_s = smem_u32(sXH);
    const uint32_t wh_s = smem_u32(sWH);

    const int lrow = lane & 15;
    const int lcol = lane >> 4;
    const int xm   = tid >> 3;    // 0..31 (m row)
    const int xseg = tid & 7;     // 0..7  (8-k segment)

    float d[2][2][4];
#pragma unroll
    for (int a = 0; a < 2; a++)
#pragma unroll
        for (int b = 0; b < 2; b++)
#pragma unroll
            for (int j = 0; j < 4; j++) d[a][b][j] = 0.0f;

    // per-warp W row base (k row = kb + wid*8 + r, col n0 + lane*4)
    const float4* Wp = reinterpret_cast<const float4*>(
        W + (size_t)(k0 + wid * 8) * DOUT + n0) + lane;
    const size_t WROW = DOUT / 4;          // float4 per k row
    const size_t WCHK = (size_t)KC * WROW; // float4 per chunk step

    // dequant one row r from w, store fp16 to smem tile
    auto dq_row = [&](float4 w, int r) {
        float b = w.x;
        if (fabsf(w.y) > fabsf(b)) b = w.y;
        if (fabsf(w.z) > fabsf(b)) b = w.z;
        if (fabsf(w.w) > fabsf(b)) b = w.w;
#pragma unroll
        for (int off = 1; off <= 4; off <<= 1) {
            float o  = __shfl_xor_sync(0xffffffffu, b, off);
            float ab = fabsf(b), ao = fabsf(o);
            bool keep = (ab > ao) || (ab == ao && (lane & off) == 0);
            b = keep ? b : o;
        }
        float dd    = b * -0.125f;                       // exact /8
        float scale = __half2float(__float2half_rn(dd)); // fp16 round-trip
        float inv   = __frcp_rn(dd);                     // == RN(1/dd)
        float n8s   = scale * -8.0f;

        float t0 = fminf(truncf(fmaf(w.x, inv, 8.5f)), 15.0f);
        float t1 = fminf(truncf(fmaf(w.y, inv, 8.5f)), 15.0f);
        float t2 = fminf(truncf(fmaf(w.z, inv, 8.5f)), 15.0f);
        float t3 = fminf(truncf(fmaf(w.w, inv, 8.5f)), 15.0f);
        float q0 = fmaf(scale, t0, n8s);
        float q1 = fmaf(scale, t1, n8s);
        float q2 = fmaf(scale, t2, n8s);
        float q3 = fmaf(scale, t3, n8s);

        uint32_t h01 = f16pack(q0, q1);
        uint32_t h23 = f16pack(q2, q3);
        const int kr = wid * 8 + r;
        uint32_t ha = wh_s + (uint32_t)(kr * WSTR + lane * 4) * 2;
        asm volatile("st.shared.v2.b32 [%0], {%1,%2};" :: "r"(ha), "r"(h01), "r"(h23) : "memory");
    };

    // front-batched W prefetch for chunk 0 (8 x LDG.128, MLP=8)
    float4 wv[8];
#pragma unroll
    for (int r = 0; r < 8; r++)
        wv[r] = Wp[(size_t)r * WROW];

#pragma unroll 1
    for (int c = 0; c < NCHUNKS; c++) {
        const int kb = k0 + c * KC;

        // ---- x chunk: fp32 -> fp16 convert on the fly (X is L2-resident) ----
        {
            const float4* xs = reinterpret_cast<const float4*>(
                X + (size_t)xm * DIN + kb + xseg * 8);
            float4 a = xs[0], bq = xs[1];
            *reinterpret_cast<uint4*>(sXH + xm * XSTR + xseg * 8) =
                make_uint4(f16pack(a.x, a.y),  f16pack(a.z, a.w),
                           f16pack(bq.x, bq.y), f16pack(bq.z, bq.w));
        }

        const bool more = (c + 1 < NCHUNKS);
        const float4* Wn = Wp + (size_t)(c + 1) * WCHK;

        // ---- half 1: dequant rows 0..3, then reload wv[0..3] for c+1 ----
        dq_row(wv[0], 0); dq_row(wv[1], 1); dq_row(wv[2], 2); dq_row(wv[3], 3);
        if (more) {
#pragma unroll
            for (int r = 0; r < 4; r++) wv[r] = Wn[(size_t)r * WROW];
        }
        // ---- half 2: dequant rows 4..7, then reload wv[4..7] for c+1 ----
        dq_row(wv[4], 4); dq_row(wv[5], 5); dq_row(wv[6], 6); dq_row(wv[7], 7);
        if (more) {
#pragma unroll
            for (int r = 4; r < 8; r++) wv[r] = Wn[(size_t)r * WROW];
        }

        __syncthreads();

        // ---- mma: warp owns n slice [wid*16, wid*16+16), single term ----
#pragma unroll
        for (int ksi = 0; ksi < 4; ksi++) {
            uint32_t ah0[4], ah1[4], bh[4];
            uint32_t arow = (uint32_t)(lrow * XSTR + ksi * 16 + lcol * 8) * 2;
            ldsm4(ah0, xh_s + arow);                       // m 0..15
            ldsm4(ah1, xh_s + arow + 16u * XSTR * 2);      // m 16..31

            uint32_t brow = (uint32_t)((ksi * 16 + lrow) * WSTR + wid * 16 + lcol * 8) * 2;
            ldsm4t(bh, wh_s + brow);

            mma_f16(d[0][0], ah0, bh);     mma_f16(d[0][1], ah0, bh + 2);
            mma_f16(d[1][0], ah1, bh);     mma_f16(d[1][1], ah1, bh + 2);
        }
        __syncthreads();
    }

    // ---- write split-k partials ----
    {
        const int g4   = lane >> 2;
        const int tid4 = lane & 3;
        float* obase = g_partial + (size_t)ks * MR * DOUT + n0 + wid * 16;
#pragma unroll
        for (int mt = 0; mt < 2; mt++) {
#pragma unroll
            for (int nt = 0; nt < 2; nt++) {
                int col = nt * 8 + tid4 * 2;
                float* p0 = obase + (size_t)(mt * 16 + g4)     * DOUT + col;
                float* p1 = obase + (size_t)(mt * 16 + g4 + 8) * DOUT + col;
                *reinterpret_cast<float2*>(p0) = make_float2(d[mt][nt][0], d[mt][nt][1]);
                *reinterpret_cast<float2*>(p1) = make_float2(d[mt][nt][2], d[mt][nt][3]);
            }
        }
    }
}

// ---------------------------------------------------------------------------
// Epilog: out = bias + sum_ks partials
// ---------------------------------------------------------------------------
__global__ void reduce_kernel(const float* __restrict__ bias, float* __restrict__ out) {
    int i = blockIdx.x * blockDim.x + threadIdx.x;   // float4 index
    if (i >= (MR * DOUT) / 4) return;
    int n4 = i & (DOUT / 4 - 1);
    float4 s = reinterpret_cast<const float4*>(bias)[n4];
#pragma unroll
    for (int k = 0; k < KSPLIT; k++) {
        float4 p = reinterpret_cast<const float4*>(g_partial + (size_t)k * MR * DOUT)[i];
        s.x += p.x; s.y += p.y; s.z += p.z; s.w += p.w;
    }
    reinterpret_cast<float4*>(out)[i] = s;
}

// ---------------------------------------------------------------------------
extern "C" void kernel_launch(void* const* d_in, const int* in_sizes, int n_in,
                              void* d_out, int out_size) {
    const float *X = nullptr, *W = nullptr, *B = nullptr;
    for (int i = 0; i < n_in; i++) {
        long long sz = in_sizes[i];
        if      (sz == (long long)DIN * DOUT) W = (const float*)d_in[i];
        else if (sz == (long long)MR * DIN)   X = (const float*)d_in[i];
        else if (sz == (long long)DOUT)       B = (const float*)d_in[i];
    }

    dim3 grid(DOUT / NTILE, KSPLIT);   // 64 x 8 = 512 CTAs
    gemm_kernel<<<grid, GTHREADS>>>(W, X);

    reduce_kernel<<<(MR * DOUT / 4 + 255) / 256, 256>>>(B, (float*)d_out);
}